// round 10
// baseline (speedup 1.0000x reference)
#include <cuda_runtime.h>
#include <cuda_bf16.h>
#include <cstdint>

#define BATCH 8192
#define TSTEPS 16
#define HID 512
#define FEAT 4
#define NGATE 2048  // 4*HID

// ---------------- static device scratch (no dynamic allocation) -------------
// h16: [buf][net][B*H], double-buffered per step (net: 0=enc_s, 1=enc_p, 2=dec)
__device__ __nv_bfloat16 g_h16[2][3][BATCH * HID];
__device__ float         g_h32[3][BATCH * HID];     // fp32 h (combine / dec tail)
__device__ float         g_cst[3][BATCH * HID];     // c state
__device__ __nv_bfloat16 g_W16[3][NGATE * HID];     // W_hh bf16, gate-interleaved rows
__device__ float         g_bias[3][NGATE];          // b_ih+b_hh, permuted
__device__ float         g_Wih[3][NGATE * FEAT];    // W_ih rows, permuted
__device__ float         g_lastpos[BATCH * FEAT];

// ---------------- sm_80-level PTX helpers (base target sm_103) --------------
static __device__ __forceinline__ uint32_t smem_u32(const void* p) {
    return (uint32_t)__cvta_generic_to_shared(p);
}
#define CP_ASYNC16(dst, src) \
    asm volatile("cp.async.cg.shared.global [%0], [%1], 16;" :: "r"(dst), "l"(src))
#define CP_COMMIT() asm volatile("cp.async.commit_group;" ::: "memory")
#define CP_WAIT0()  asm volatile("cp.async.wait_group 0;" ::: "memory")
#define CP_WAIT1()  asm volatile("cp.async.wait_group 1;" ::: "memory")

static __device__ __forceinline__ void ldsm_x4(uint32_t* r, uint32_t addr) {
    asm volatile("ldmatrix.sync.aligned.m8n8.x4.shared.b16 {%0,%1,%2,%3}, [%4];"
                 : "=r"(r[0]), "=r"(r[1]), "=r"(r[2]), "=r"(r[3]) : "r"(addr));
}
static __device__ __forceinline__ void ldsm_x2(uint32_t* r, uint32_t addr) {
    asm volatile("ldmatrix.sync.aligned.m8n8.x2.shared.b16 {%0,%1}, [%2];"
                 : "=r"(r[0]), "=r"(r[1]) : "r"(addr));
}
static __device__ __forceinline__ void mma_bf16(float* d, const uint32_t* a,
                                                const uint32_t* b) {
    asm volatile(
        "mma.sync.aligned.m16n8k16.row.col.f32.bf16.bf16.f32 "
        "{%0,%1,%2,%3}, {%4,%5,%6,%7}, {%8,%9}, {%0,%1,%2,%3};"
        : "+f"(d[0]), "+f"(d[1]), "+f"(d[2]), "+f"(d[3])
        : "r"(a[0]), "r"(a[1]), "r"(a[2]), "r"(a[3]), "r"(b[0]), "r"(b[1]));
}
static __device__ __forceinline__ uint32_t sw64(uint32_t off) {
    return off ^ ((off >> 3) & 0x30);
}
static __device__ __forceinline__ float sigf(float x) { return 1.0f / (1.0f + expf(-x)); }

// ---------------------------------------------------------------------------
// Fused GEMM + LSTM cell step.  3-stage cp.async pipeline, 1 sync/chunk,
// 2 CTAs/SM (launch_bounds).  D[m,n'] = sum_k h[m,k]*Wp[n',k], n' = j*4+gi.
// Epilogue: gates + bias + x.Wih -> cell update -> c, h32, h16_dst.
// mode 0: encoders (blockIdx.z = net 0/1); mode 1: decoder (net 2, x=lastpos).
// ---------------------------------------------------------------------------
__global__ void __launch_bounds__(256, 2)
gemm_step(int mode, int srcbuf, int dstbuf, int t,
          const float* __restrict__ speed, const float* __restrict__ pos)
{
    const int net = (mode == 0) ? (int)blockIdx.z : 2;
    const __nv_bfloat16* A = g_h16[srcbuf][net];
    const __nv_bfloat16* W = g_W16[net];

    const int n0 = blockIdx.x * 128;
    const int m0 = blockIdx.y * 128;
    const int tid  = threadIdx.x;
    const int lane = tid & 31;
    const int warp = tid >> 5;
    const int wm = warp >> 2;   // 0..1
    const int wn = warp & 3;    // 0..3

    __shared__ __align__(1024) unsigned char sm[49152];  // 3 stages x 16KB
    const uint32_t smBase = smem_u32(sm);

    const uint4* A4 = reinterpret_cast<const uint4*>(A);
    const uint4* W4 = reinterpret_cast<const uint4*>(W);

    const int cu  = tid & 3;
    const int cr0 = tid >> 2;
    const uint32_t swoA0 = sw64((uint32_t)(cr0 * 64 + cu * 16));
    const uint32_t swoA1 = sw64((uint32_t)((cr0 + 64) * 64 + cu * 16));

    uint32_t aOff[4][2], bOff[4][2];
    {
        int l = lane;
        #pragma unroll
        for (int fm = 0; fm < 4; ++fm) {
            int r = wm * 64 + fm * 16 + (l & 15);
            #pragma unroll
            for (int kk = 0; kk < 2; ++kk)
                aOff[fm][kk] = sw64((uint32_t)(r * 64 + kk * 32 + ((l >> 4) & 1) * 16));
        }
        int l2 = lane & 15;
        #pragma unroll
        for (int fn = 0; fn < 4; ++fn) {
            int r = wn * 32 + fn * 8 + (l2 & 7);
            #pragma unroll
            for (int kk = 0; kk < 2; ++kk)
                bOff[fn][kk] =
                    8192u + sw64((uint32_t)(r * 64 + kk * 32 + ((l2 >> 3) & 1) * 16));
        }
    }

    float d[4][4][4];
    #pragma unroll
    for (int i = 0; i < 4; ++i)
        #pragma unroll
        for (int j = 0; j < 4; ++j)
            #pragma unroll
            for (int q = 0; q < 4; ++q) d[i][j][q] = 0.0f;

    // issue one K-chunk (32 wide) into a stage; one commit group per chunk
    auto issue = [&](int ch, int stage) {
        uint32_t st = smBase + (uint32_t)(stage * 16384);
        int ko = ch * 4;
        CP_ASYNC16(st + swoA0,         (const void*)(A4 + (size_t)(m0 + cr0)      * 64 + ko + cu));
        CP_ASYNC16(st + swoA1,         (const void*)(A4 + (size_t)(m0 + cr0 + 64) * 64 + ko + cu));
        CP_ASYNC16(st + 8192u + swoA0, (const void*)(W4 + (size_t)(n0 + cr0)      * 64 + ko + cu));
        CP_ASYNC16(st + 8192u + swoA1, (const void*)(W4 + (size_t)(n0 + cr0 + 64) * 64 + ko + cu));
        CP_COMMIT();
    };

    issue(0, 0);
    issue(1, 1);

    int stage = 0;
    for (int c = 0; c < 16; ++c) {
        CP_WAIT1();          // group for chunk c complete (<=1 pending)
        __syncthreads();     // all threads' chunk-c data visible; prev compute done
        if (c < 14) {
            int s2 = stage + 2; if (s2 >= 3) s2 -= 3;
            issue(c + 2, s2);
        }

        const uint32_t st = smBase + (uint32_t)(stage * 16384);
        #pragma unroll
        for (int kk = 0; kk < 2; ++kk) {
            uint32_t a[4][4], b[4][2];
            #pragma unroll
            for (int fm = 0; fm < 4; ++fm) ldsm_x4(a[fm], st + aOff[fm][kk]);
            #pragma unroll
            for (int fn = 0; fn < 4; ++fn) ldsm_x2(b[fn], st + bOff[fn][kk]);
            #pragma unroll
            for (int fm = 0; fm < 4; ++fm)
                #pragma unroll
                for (int fn = 0; fn < 4; ++fn) mma_bf16(d[fm][fn], a[fm], b[fn]);
        }
        if (++stage == 3) stage = 0;
    }
    __syncthreads();   // all compute done before smem reuse below

    // ---- fused epilogue: stage x (4/row), bias, Wih into smem --------------
    float* smx = reinterpret_cast<float*>(sm);          // 128*4 floats
    float* smb = reinterpret_cast<float*>(sm + 2048);   // 128 floats
    float* smw = reinterpret_cast<float*>(sm + 4096);   // 128*4 floats

    if (tid < 128) smb[tid] = g_bias[net][n0 + tid];
    {
        const float* xb = (mode == 0) ? (net ? pos : speed) : nullptr;
        #pragma unroll
        for (int i = 0; i < 2; ++i) {
            int idx = tid + i * 256;         // 0..511
            smw[idx] = g_Wih[net][n0 * 4 + idx];
            int rr = idx >> 2, q = idx & 3;
            smx[idx] = (mode == 0)
                ? xb[(size_t)(m0 + rr) * (TSTEPS * FEAT) + t * FEAT + q]
                : g_lastpos[(m0 + rr) * 4 + q];
        }
    }
    __syncthreads();

    float* cstate = g_cst[net];
    float* h32    = g_h32[net];
    __nv_bfloat16* hdst = g_h16[dstbuf][net];

    const int rbase = wm * 64 + (lane >> 2);
    const int odd   = lane & 1;
    #pragma unroll
    for (int fm = 0; fm < 4; ++fm) {
        #pragma unroll
        for (int fn = 0; fn < 4; ++fn) {
            const int cl = wn * 32 + fn * 8 + (lane & 3) * 2;  // local col n'
            const float b0 = smb[cl], b1 = smb[cl + 1];
            float v[2][2];
            #pragma unroll
            for (int half = 0; half < 2; ++half) {
                const int rloc = rbase + fm * 16 + half * 8;
                const float x0 = smx[rloc * 4 + 0], x1 = smx[rloc * 4 + 1];
                const float x2 = smx[rloc * 4 + 2], x3 = smx[rloc * 4 + 3];
                v[half][0] = d[fm][fn][half * 2 + 0] + b0
                           + x0 * smw[cl * 4 + 0] + x1 * smw[cl * 4 + 1]
                           + x2 * smw[cl * 4 + 2] + x3 * smw[cl * 4 + 3];
                v[half][1] = d[fm][fn][half * 2 + 1] + b1
                           + x0 * smw[(cl + 1) * 4 + 0] + x1 * smw[(cl + 1) * 4 + 1]
                           + x2 * smw[(cl + 1) * 4 + 2] + x3 * smw[(cl + 1) * 4 + 3];
            }
            // exchange with lane^1: even lanes own (i,f), odd lanes own (g,o)
            float q00 = __shfl_xor_sync(0xFFFFFFFFu, v[0][0], 1);
            float q01 = __shfl_xor_sync(0xFFFFFFFFu, v[0][1], 1);
            float q10 = __shfl_xor_sync(0xFFFFFFFFu, v[1][0], 1);
            float q11 = __shfl_xor_sync(0xFFFFFFFFu, v[1][1], 1);
            // even lane processes row-half 0, odd lane row-half 1 (balanced)
            float gi_, gf_, gg_, go_;
            int jcl;
            if (!odd) { gi_ = v[0][0]; gf_ = v[0][1]; gg_ = q00; go_ = q01; jcl = cl; }
            else      { gi_ = q10;     gf_ = q11;     gg_ = v[1][0]; go_ = v[1][1]; jcl = cl - 2; }
            const int rloc = rbase + fm * 16 + odd * 8;
            const int j    = (n0 + jcl) >> 2;
            const size_t li = (size_t)(m0 + rloc) * HID + j;
            float cold = cstate[li];
            float cn = sigf(gf_) * cold + sigf(gi_) * tanhf(gg_);
            float h  = sigf(go_) * tanhf(cn);
            cstate[li] = cn;
            h32[li]    = h;
            hdst[li]   = __float2bfloat16(h);
        }
    }
}

// ---------------------------------------------------------------------------
// prep: permute W_hh rows to n'=j*4+gi (bf16); bias/Wih permuted by row `lin`.
// ---------------------------------------------------------------------------
__global__ void __launch_bounds__(256)
prep_kernel(const float* __restrict__ Ws_hh, const float* __restrict__ Wp_hh,
            const float* __restrict__ Wd_hh,
            const float* __restrict__ Ws_ih, const float* __restrict__ Wp_ih,
            const float* __restrict__ Wd_ih,
            const float* __restrict__ bs_ih, const float* __restrict__ bs_hh,
            const float* __restrict__ bp_ih, const float* __restrict__ bp_hh,
            const float* __restrict__ bd_ih, const float* __restrict__ bd_hh)
{
    int lin = blockIdx.x * 256 + threadIdx.x;    // 0 .. NGATE*HID-1
    int np = lin / HID;                          // permuted row n'
    int k  = lin - np * HID;
    int j  = np >> 2, gi = np & 3;
    int n  = gi * HID + j;                       // original row
    size_t src = (size_t)n * HID + k;
    g_W16[0][lin] = __float2bfloat16(Ws_hh[src]);
    g_W16[1][lin] = __float2bfloat16(Wp_hh[src]);
    g_W16[2][lin] = __float2bfloat16(Wd_hh[src]);
    if (lin < NGATE) {
        int jj = lin >> 2, gg = lin & 3;
        int nn = gg * HID + jj;                  // original row for permuted row `lin`
        g_bias[0][lin] = bs_ih[nn] + bs_hh[nn];
        g_bias[1][lin] = bp_ih[nn] + bp_hh[nn];
        g_bias[2][lin] = bd_ih[nn] + bd_hh[nn];
        #pragma unroll
        for (int q = 0; q < 4; ++q) {
            g_Wih[0][lin * 4 + q] = Ws_ih[nn * 4 + q];
            g_Wih[1][lin * 4 + q] = Wp_ih[nn * 4 + q];
            g_Wih[2][lin * 4 + q] = Wd_ih[nn * 4 + q];
        }
    }
}

// Encoder step 0 (h=c=0): gates = bias + x.Wih ; writes c, h32, h16[1]
__global__ void __launch_bounds__(256)
enc0_kernel(const float* __restrict__ speed, const float* __restrict__ pos)
{
    const int e = blockIdx.y;
    const float* x = e ? pos : speed;
    int lin = blockIdx.x * 256 + threadIdx.x;
    int b = lin >> 9, j = lin & 511;

    const float* xr = x + b * (TSTEPS * FEAT);   // t = 0
    float x0 = xr[0], x1 = xr[1], x2 = xr[2], x3 = xr[3];

    float gate[4];
    #pragma unroll
    for (int gi = 0; gi < 4; ++gi) {
        int np = j * 4 + gi;
        const float* wr = &g_Wih[e][np * 4];
        gate[gi] = g_bias[e][np] + x0 * wr[0] + x1 * wr[1] + x2 * wr[2] + x3 * wr[3];
    }
    float cn = sigf(gate[0]) * tanhf(gate[2]);   // c_old = 0
    float h  = sigf(gate[3]) * tanhf(cn);
    g_cst[e][lin] = cn;
    g_h32[e][lin] = h;
    g_h16[1][e][lin] = __float2bfloat16(h);
}

__global__ void __launch_bounds__(256)
combine_kernel(const float* __restrict__ pos)
{
    int lin = blockIdx.x * 256 + threadIdx.x;
    g_h16[0][2][lin] = __float2bfloat16(g_h32[0][lin] + g_h32[1][lin]);
    g_cst[2][lin] = g_cst[0][lin] + g_cst[1][lin];
    int b = lin >> 9, j = lin & 511;
    if (j < FEAT)
        g_lastpos[b * FEAT + j] = pos[b * (TSTEPS * FEAT) + (TSTEPS - 1) * FEAT + j];
}

// Decoder tail: fc reduce + softmax + emb + lastpos update (reads h32[2])
__global__ void __launch_bounds__(512)
dec_tail_kernel(const float* __restrict__ W_fc, const float* __restrict__ b_fc,
                const float* __restrict__ W_emb, const float* __restrict__ b_emb,
                float* __restrict__ out, int t)
{
    const int b = blockIdx.x;
    const int j = threadIdx.x;
    float h = g_h32[2][(size_t)b * HID + j];

    float s0 = h * W_fc[j];
    float s1 = h * W_fc[HID + j];
    #pragma unroll
    for (int off = 16; off > 0; off >>= 1) {
        s0 += __shfl_xor_sync(0xFFFFFFFFu, s0, off);
        s1 += __shfl_xor_sync(0xFFFFFFFFu, s1, off);
    }
    __shared__ float r0[16], r1[16];
    if ((j & 31) == 0) { r0[j >> 5] = s0; r1[j >> 5] = s1; }
    __syncthreads();
    if (j == 0) {
        float t0 = 0.f, t1 = 0.f;
        #pragma unroll
        for (int w = 0; w < 16; ++w) { t0 += r0[w]; t1 += r1[w]; }
        float c0 = fmaxf(t0 + b_fc[0], 0.f);
        float c1 = fmaxf(t1 + b_fc[1], 0.f);
        float m = fmaxf(c0, c1);
        float e0 = expf(c0 - m), e1 = expf(c1 - m);
        float inv = 1.f / (e0 + e1);
        out[((size_t)b * TSTEPS + t) * 2 + 0] = e0 * inv;
        out[((size_t)b * TSTEPS + t) * 2 + 1] = e1 * inv;
        #pragma unroll
        for (int k = 0; k < 4; ++k)
            g_lastpos[b * 4 + k] =
                fmaxf(c0 * W_emb[k * 2 + 0] + c1 * W_emb[k * 2 + 1] + b_emb[k], 0.f);
    }
}

// ---------------- orchestration ---------------------------------------------
extern "C" void kernel_launch(void* const* d_in, const int* in_sizes, int n_in,
                              void* d_out, int out_size)
{
    (void)in_sizes; (void)n_in; (void)out_size;
    const float* speed = (const float*)d_in[0];
    const float* pos   = (const float*)d_in[1];
    const float* Ws_ih = (const float*)d_in[2];
    const float* Ws_hh = (const float*)d_in[3];
    const float* bs_ih = (const float*)d_in[4];
    const float* bs_hh = (const float*)d_in[5];
    const float* Wp_ih = (const float*)d_in[6];
    const float* Wp_hh = (const float*)d_in[7];
    const float* bp_ih = (const float*)d_in[8];
    const float* bp_hh = (const float*)d_in[9];
    const float* Wd_ih = (const float*)d_in[10];
    const float* Wd_hh = (const float*)d_in[11];
    const float* bd_ih = (const float*)d_in[12];
    const float* bd_hh = (const float*)d_in[13];
    const float* W_fc  = (const float*)d_in[14];
    const float* b_fc  = (const float*)d_in[15];
    const float* W_emb = (const float*)d_in[16];
    const float* b_emb = (const float*)d_in[17];
    float* out = (float*)d_out;

    const int nPW = (BATCH * HID) / 256;   // 16384 blocks

    prep_kernel<<<NGATE * HID / 256, 256>>>(Ws_hh, Wp_hh, Wd_hh,
                                            Ws_ih, Wp_ih, Wd_ih,
                                            bs_ih, bs_hh, bp_ih, bp_hh, bd_ih, bd_hh);
    enc0_kernel<<<dim3(nPW, 2), 256>>>(speed, pos);

    for (int t = 1; t < TSTEPS; ++t)
        gemm_step<<<dim3(NGATE / 128, BATCH / 128, 2), 256>>>(
            0, t & 1, (t + 1) & 1, t, speed, pos);

    combine_kernel<<<nPW, 256>>>(pos);

    for (int t = 0; t < TSTEPS; ++t) {
        gemm_step<<<dim3(NGATE / 128, BATCH / 128, 1), 256>>>(
            1, t & 1, (t + 1) & 1, t, speed, pos);
        dec_tail_kernel<<<BATCH, 512>>>(W_fc, b_fc, W_emb, b_emb, out, t);
    }
}

// round 12
// speedup vs baseline: 2.3245x; 2.3245x over previous
#include <cuda_runtime.h>
#include <cuda_bf16.h>
#include <cstdint>

#define BATCH 8192
#define TSTEPS 16
#define HID 512
#define FEAT 4
#define NGATE 2048  // 4*HID

// ---------------- static device scratch (no dynamic allocation) -------------
// h16: [buf][net][B*H], double-buffered per step (net: 0=enc_s, 1=enc_p, 2=dec)
__device__ __nv_bfloat16 g_h16[2][3][BATCH * HID];
__device__ float         g_h32[3][BATCH * HID];     // fp32 h (combine / dec tail)
__device__ float         g_cst[3][BATCH * HID];     // c state
__device__ __nv_bfloat16 g_W16[3][NGATE * HID];     // W_hh bf16, gate-interleaved rows
__device__ float         g_bias[3][NGATE];          // b_ih+b_hh, permuted
__device__ float         g_Wih[3][NGATE * FEAT];    // W_ih rows, permuted
__device__ float         g_lastpos[BATCH * FEAT];

// ---------------- sm_80-level PTX helpers (base target sm_103) --------------
static __device__ __forceinline__ uint32_t smem_u32(const void* p) {
    return (uint32_t)__cvta_generic_to_shared(p);
}
#define CP_ASYNC16(dst, src) \
    asm volatile("cp.async.cg.shared.global [%0], [%1], 16;" :: "r"(dst), "l"(src))
#define CP_COMMIT() asm volatile("cp.async.commit_group;" ::: "memory")
#define CP_WAIT0()  asm volatile("cp.async.wait_group 0;" ::: "memory")
#define CP_WAIT1()  asm volatile("cp.async.wait_group 1;" ::: "memory")

static __device__ __forceinline__ void ldsm_x4(uint32_t* r, uint32_t addr) {
    asm volatile("ldmatrix.sync.aligned.m8n8.x4.shared.b16 {%0,%1,%2,%3}, [%4];"
                 : "=r"(r[0]), "=r"(r[1]), "=r"(r[2]), "=r"(r[3]) : "r"(addr));
}
static __device__ __forceinline__ void ldsm_x2(uint32_t* r, uint32_t addr) {
    asm volatile("ldmatrix.sync.aligned.m8n8.x2.shared.b16 {%0,%1}, [%2];"
                 : "=r"(r[0]), "=r"(r[1]) : "r"(addr));
}
static __device__ __forceinline__ void mma_bf16(float* d, const uint32_t* a,
                                                const uint32_t* b) {
    asm volatile(
        "mma.sync.aligned.m16n8k16.row.col.f32.bf16.bf16.f32 "
        "{%0,%1,%2,%3}, {%4,%5,%6,%7}, {%8,%9}, {%0,%1,%2,%3};"
        : "+f"(d[0]), "+f"(d[1]), "+f"(d[2]), "+f"(d[3])
        : "r"(a[0]), "r"(a[1]), "r"(a[2]), "r"(a[3]), "r"(b[0]), "r"(b[1]));
}
static __device__ __forceinline__ uint32_t sw64(uint32_t off) {
    return off ^ ((off >> 3) & 0x30);
}
static __device__ __forceinline__ float sigf(float x) { return 1.0f / (1.0f + expf(-x)); }

// ---------------------------------------------------------------------------
// Fused GEMM + LSTM cell step.  3-stage cp.async pipeline (CP_WAIT0 on the
// final chunk — R10 raced it), 2 CTAs/SM.  D[m,n'] = sum_k h[m,k]*Wp[n',k],
// n' = j*4+gi.  Epilogue is fully COALESCED via smem staging of the CTA's
// dense [128 x 32] (row, j) output block.
// mode 0: encoders (blockIdx.z = net 0/1); mode 1: decoder (net 2, x=lastpos).
// ---------------------------------------------------------------------------
__global__ void __launch_bounds__(256, 2)
gemm_step(int mode, int srcbuf, int dstbuf, int t,
          const float* __restrict__ speed, const float* __restrict__ pos)
{
    const int net = (mode == 0) ? (int)blockIdx.z : 2;
    const __nv_bfloat16* A = g_h16[srcbuf][net];
    const __nv_bfloat16* W = g_W16[net];

    const int n0 = blockIdx.x * 128;
    const int jbase = blockIdx.x * 32;          // j range covered by this CTA
    const int m0 = blockIdx.y * 128;
    const int tid  = threadIdx.x;
    const int lane = tid & 31;
    const int warp = tid >> 5;
    const int wm = warp >> 2;   // 0..1
    const int wn = warp & 3;    // 0..3

    __shared__ __align__(1024) unsigned char sm[49152];  // 3 stages x 16KB
    const uint32_t smBase = smem_u32(sm);

    const uint4* A4 = reinterpret_cast<const uint4*>(A);
    const uint4* W4 = reinterpret_cast<const uint4*>(W);

    const int cu  = tid & 3;
    const int cr0 = tid >> 2;
    const uint32_t swoA0 = sw64((uint32_t)(cr0 * 64 + cu * 16));
    const uint32_t swoA1 = sw64((uint32_t)((cr0 + 64) * 64 + cu * 16));

    uint32_t aOff[4][2], bOff[4][2];
    {
        int l = lane;
        #pragma unroll
        for (int fm = 0; fm < 4; ++fm) {
            int r = wm * 64 + fm * 16 + (l & 15);
            #pragma unroll
            for (int kk = 0; kk < 2; ++kk)
                aOff[fm][kk] = sw64((uint32_t)(r * 64 + kk * 32 + ((l >> 4) & 1) * 16));
        }
        int l2 = lane & 15;
        #pragma unroll
        for (int fn = 0; fn < 4; ++fn) {
            int r = wn * 32 + fn * 8 + (l2 & 7);
            #pragma unroll
            for (int kk = 0; kk < 2; ++kk)
                bOff[fn][kk] =
                    8192u + sw64((uint32_t)(r * 64 + kk * 32 + ((l2 >> 3) & 1) * 16));
        }
    }

    float d[4][4][4];
    #pragma unroll
    for (int i = 0; i < 4; ++i)
        #pragma unroll
        for (int j = 0; j < 4; ++j)
            #pragma unroll
            for (int q = 0; q < 4; ++q) d[i][j][q] = 0.0f;

    auto issue = [&](int ch, int stage) {
        uint32_t st = smBase + (uint32_t)(stage * 16384);
        int ko = ch * 4;
        CP_ASYNC16(st + swoA0,         (const void*)(A4 + (size_t)(m0 + cr0)      * 64 + ko + cu));
        CP_ASYNC16(st + swoA1,         (const void*)(A4 + (size_t)(m0 + cr0 + 64) * 64 + ko + cu));
        CP_ASYNC16(st + 8192u + swoA0, (const void*)(W4 + (size_t)(n0 + cr0)      * 64 + ko + cu));
        CP_ASYNC16(st + 8192u + swoA1, (const void*)(W4 + (size_t)(n0 + cr0 + 64) * 64 + ko + cu));
        CP_COMMIT();
    };

    issue(0, 0);
    issue(1, 1);

    int stage = 0;
    for (int c = 0; c < 16; ++c) {
        if (c < 15) { CP_WAIT1(); }   // chunk c complete; chunk c+1 may be in flight
        else        { CP_WAIT0(); }   // FINAL chunk: must drain fully (R10 bug)
        __syncthreads();              // chunk-c data visible; prev compute done
        if (c < 14) {
            int s2 = stage + 2; if (s2 >= 3) s2 -= 3;
            issue(c + 2, s2);
        }

        const uint32_t st = smBase + (uint32_t)(stage * 16384);
        #pragma unroll
        for (int kk = 0; kk < 2; ++kk) {
            uint32_t a[4][4], b[4][2];
            #pragma unroll
            for (int fm = 0; fm < 4; ++fm) ldsm_x4(a[fm], st + aOff[fm][kk]);
            #pragma unroll
            for (int fn = 0; fn < 4; ++fn) ldsm_x2(b[fn], st + bOff[fn][kk]);
            #pragma unroll
            for (int fm = 0; fm < 4; ++fm)
                #pragma unroll
                for (int fn = 0; fn < 4; ++fn) mma_bf16(d[fm][fn], a[fm], b[fn]);
        }
        if (++stage == 3) stage = 0;
    }
    __syncthreads();   // all compute + cp.async done before smem reuse below

    // ---- fused epilogue, fully coalesced via smem staging ------------------
    // layout (bytes): cbuf[128][33] @0 (16896), hbuf[128][33] @16896 (16896),
    //                 smx[512] @33792, smb[128] @35840, smw[512] @36352
    float* cbuf = reinterpret_cast<float*>(sm);
    float* hbuf = reinterpret_cast<float*>(sm + 16896);
    float* smx  = reinterpret_cast<float*>(sm + 33792);
    float* smb  = reinterpret_cast<float*>(sm + 35840);
    float* smw  = reinterpret_cast<float*>(sm + 36352);

    float* cstate = g_cst[net];
    float* h32    = g_h32[net];
    __nv_bfloat16* hdst = g_h16[dstbuf][net];

    // Phase A: coalesced loads of c_old block + x, bias, Wih
    #pragma unroll
    for (int i = 0; i < 16; ++i) {
        int idx = tid + i * 256;             // 0..4095
        int r = idx >> 5, cc = idx & 31;
        cbuf[r * 33 + cc] = cstate[(size_t)(m0 + r) * HID + jbase + cc];
    }
    if (tid < 128) smb[tid] = g_bias[net][n0 + tid];
    {
        const float* xb = (mode == 0) ? (net ? pos : speed) : nullptr;
        #pragma unroll
        for (int i = 0; i < 2; ++i) {
            int idx = tid + i * 256;         // 0..511
            smw[idx] = g_Wih[net][n0 * 4 + idx];
            int rr = idx >> 2, q = idx & 3;
            smx[idx] = (mode == 0)
                ? xb[(size_t)(m0 + rr) * (TSTEPS * FEAT) + t * FEAT + q]
                : g_lastpos[(m0 + rr) * 4 + q];
        }
    }
    __syncthreads();

    // Phase B: cell updates entirely in registers/smem
    const int rbase = wm * 64 + (lane >> 2);
    const int odd   = lane & 1;
    #pragma unroll
    for (int fm = 0; fm < 4; ++fm) {
        #pragma unroll
        for (int fn = 0; fn < 4; ++fn) {
            const int cl = wn * 32 + fn * 8 + (lane & 3) * 2;  // local col n'
            const float b0 = smb[cl], b1 = smb[cl + 1];
            float v[2][2];
            #pragma unroll
            for (int half = 0; half < 2; ++half) {
                const int rloc = rbase + fm * 16 + half * 8;
                const float x0 = smx[rloc * 4 + 0], x1 = smx[rloc * 4 + 1];
                const float x2 = smx[rloc * 4 + 2], x3 = smx[rloc * 4 + 3];
                v[half][0] = d[fm][fn][half * 2 + 0] + b0
                           + x0 * smw[cl * 4 + 0] + x1 * smw[cl * 4 + 1]
                           + x2 * smw[cl * 4 + 2] + x3 * smw[cl * 4 + 3];
                v[half][1] = d[fm][fn][half * 2 + 1] + b1
                           + x0 * smw[(cl + 1) * 4 + 0] + x1 * smw[(cl + 1) * 4 + 1]
                           + x2 * smw[(cl + 1) * 4 + 2] + x3 * smw[(cl + 1) * 4 + 3];
            }
            // exchange with lane^1: even lanes own (i,f), odd lanes own (g,o)
            float q00 = __shfl_xor_sync(0xFFFFFFFFu, v[0][0], 1);
            float q01 = __shfl_xor_sync(0xFFFFFFFFu, v[0][1], 1);
            float q10 = __shfl_xor_sync(0xFFFFFFFFu, v[1][0], 1);
            float q11 = __shfl_xor_sync(0xFFFFFFFFu, v[1][1], 1);
            float gi_, gf_, gg_, go_;
            int jcl;
            if (!odd) { gi_ = v[0][0]; gf_ = v[0][1]; gg_ = q00; go_ = q01; jcl = cl; }
            else      { gi_ = q10;     gf_ = q11;     gg_ = v[1][0]; go_ = v[1][1]; jcl = cl - 2; }
            const int rloc = rbase + fm * 16 + odd * 8;
            const int jloc = jcl >> 2;                  // 0..31
            const int si = rloc * 33 + jloc;
            float cold = cbuf[si];
            float cn = sigf(gf_) * cold + sigf(gi_) * tanhf(gg_);
            float h  = sigf(go_) * tanhf(cn);
            cbuf[si] = cn;                              // in-place: touched once
            hbuf[si] = h;
        }
    }
    __syncthreads();

    // Phase C: coalesced stores of c, h32, h16
    #pragma unroll
    for (int i = 0; i < 16; ++i) {
        int idx = tid + i * 256;
        int r = idx >> 5, cc = idx & 31;
        float cv = cbuf[r * 33 + cc];
        float hv = hbuf[r * 33 + cc];
        size_t gidx = (size_t)(m0 + r) * HID + jbase + cc;
        cstate[gidx] = cv;
        h32[gidx]    = hv;
        hdst[gidx]   = __float2bfloat16(hv);
    }
}

// ---------------------------------------------------------------------------
// prep: permute W_hh rows to n'=j*4+gi (bf16); bias/Wih permuted by row `lin`.
// ---------------------------------------------------------------------------
__global__ void __launch_bounds__(256)
prep_kernel(const float* __restrict__ Ws_hh, const float* __restrict__ Wp_hh,
            const float* __restrict__ Wd_hh,
            const float* __restrict__ Ws_ih, const float* __restrict__ Wp_ih,
            const float* __restrict__ Wd_ih,
            const float* __restrict__ bs_ih, const float* __restrict__ bs_hh,
            const float* __restrict__ bp_ih, const float* __restrict__ bp_hh,
            const float* __restrict__ bd_ih, const float* __restrict__ bd_hh)
{
    int lin = blockIdx.x * 256 + threadIdx.x;    // 0 .. NGATE*HID-1
    int np = lin / HID;                          // permuted row n'
    int k  = lin - np * HID;
    int j  = np >> 2, gi = np & 3;
    int n  = gi * HID + j;                       // original row
    size_t src = (size_t)n * HID + k;
    g_W16[0][lin] = __float2bfloat16(Ws_hh[src]);
    g_W16[1][lin] = __float2bfloat16(Wp_hh[src]);
    g_W16[2][lin] = __float2bfloat16(Wd_hh[src]);
    if (lin < NGATE) {
        int jj = lin >> 2, gg = lin & 3;
        int nn = gg * HID + jj;                  // original row for permuted row `lin`
        g_bias[0][lin] = bs_ih[nn] + bs_hh[nn];
        g_bias[1][lin] = bp_ih[nn] + bp_hh[nn];
        g_bias[2][lin] = bd_ih[nn] + bd_hh[nn];
        #pragma unroll
        for (int q = 0; q < 4; ++q) {
            g_Wih[0][lin * 4 + q] = Ws_ih[nn * 4 + q];
            g_Wih[1][lin * 4 + q] = Wp_ih[nn * 4 + q];
            g_Wih[2][lin * 4 + q] = Wd_ih[nn * 4 + q];
        }
    }
}

// Encoder step 0 (h=c=0): gates = bias + x.Wih ; writes c, h32, h16[1]
__global__ void __launch_bounds__(256)
enc0_kernel(const float* __restrict__ speed, const float* __restrict__ pos)
{
    const int e = blockIdx.y;
    const float* x = e ? pos : speed;
    int lin = blockIdx.x * 256 + threadIdx.x;
    int b = lin >> 9, j = lin & 511;

    const float* xr = x + b * (TSTEPS * FEAT);   // t = 0
    float x0 = xr[0], x1 = xr[1], x2 = xr[2], x3 = xr[3];

    float gate[4];
    #pragma unroll
    for (int gi = 0; gi < 4; ++gi) {
        int np = j * 4 + gi;
        const float* wr = &g_Wih[e][np * 4];
        gate[gi] = g_bias[e][np] + x0 * wr[0] + x1 * wr[1] + x2 * wr[2] + x3 * wr[3];
    }
    float cn = sigf(gate[0]) * tanhf(gate[2]);   // c_old = 0
    float h  = sigf(gate[3]) * tanhf(cn);
    g_cst[e][lin] = cn;
    g_h32[e][lin] = h;
    g_h16[1][e][lin] = __float2bfloat16(h);
}

__global__ void __launch_bounds__(256)
combine_kernel(const float* __restrict__ pos)
{
    int lin = blockIdx.x * 256 + threadIdx.x;
    g_h16[0][2][lin] = __float2bfloat16(g_h32[0][lin] + g_h32[1][lin]);
    g_cst[2][lin] = g_cst[0][lin] + g_cst[1][lin];
    int b = lin >> 9, j = lin & 511;
    if (j < FEAT)
        g_lastpos[b * FEAT + j] = pos[b * (TSTEPS * FEAT) + (TSTEPS - 1) * FEAT + j];
}

// Decoder tail: fc reduce + softmax + emb + lastpos update (reads h32[2])
__global__ void __launch_bounds__(512)
dec_tail_kernel(const float* __restrict__ W_fc, const float* __restrict__ b_fc,
                const float* __restrict__ W_emb, const float* __restrict__ b_emb,
                float* __restrict__ out, int t)
{
    const int b = blockIdx.x;
    const int j = threadIdx.x;
    float h = g_h32[2][(size_t)b * HID + j];

    float s0 = h * W_fc[j];
    float s1 = h * W_fc[HID + j];
    #pragma unroll
    for (int off = 16; off > 0; off >>= 1) {
        s0 += __shfl_xor_sync(0xFFFFFFFFu, s0, off);
        s1 += __shfl_xor_sync(0xFFFFFFFFu, s1, off);
    }
    __shared__ float r0[16], r1[16];
    if ((j & 31) == 0) { r0[j >> 5] = s0; r1[j >> 5] = s1; }
    __syncthreads();
    if (j == 0) {
        float t0 = 0.f, t1 = 0.f;
        #pragma unroll
        for (int w = 0; w < 16; ++w) { t0 += r0[w]; t1 += r1[w]; }
        float c0 = fmaxf(t0 + b_fc[0], 0.f);
        float c1 = fmaxf(t1 + b_fc[1], 0.f);
        float m = fmaxf(c0, c1);
        float e0 = expf(c0 - m), e1 = expf(c1 - m);
        float inv = 1.f / (e0 + e1);
        out[((size_t)b * TSTEPS + t) * 2 + 0] = e0 * inv;
        out[((size_t)b * TSTEPS + t) * 2 + 1] = e1 * inv;
        #pragma unroll
        for (int k = 0; k < 4; ++k)
            g_lastpos[b * 4 + k] =
                fmaxf(c0 * W_emb[k * 2 + 0] + c1 * W_emb[k * 2 + 1] + b_emb[k], 0.f);
    }
}

// ---------------- orchestration ---------------------------------------------
extern "C" void kernel_launch(void* const* d_in, const int* in_sizes, int n_in,
                              void* d_out, int out_size)
{
    (void)in_sizes; (void)n_in; (void)out_size;
    const float* speed = (const float*)d_in[0];
    const float* pos   = (const float*)d_in[1];
    const float* Ws_ih = (const float*)d_in[2];
    const float* Ws_hh = (const float*)d_in[3];
    const float* bs_ih = (const float*)d_in[4];
    const float* bs_hh = (const float*)d_in[5];
    const float* Wp_ih = (const float*)d_in[6];
    const float* Wp_hh = (const float*)d_in[7];
    const float* bp_ih = (const float*)d_in[8];
    const float* bp_hh = (const float*)d_in[9];
    const float* Wd_ih = (const float*)d_in[10];
    const float* Wd_hh = (const float*)d_in[11];
    const float* bd_ih = (const float*)d_in[12];
    const float* bd_hh = (const float*)d_in[13];
    const float* W_fc  = (const float*)d_in[14];
    const float* b_fc  = (const float*)d_in[15];
    const float* W_emb = (const float*)d_in[16];
    const float* b_emb = (const float*)d_in[17];
    float* out = (float*)d_out;

    const int nPW = (BATCH * HID) / 256;   // 16384 blocks

    prep_kernel<<<NGATE * HID / 256, 256>>>(Ws_hh, Wp_hh, Wd_hh,
                                            Ws_ih, Wp_ih, Wd_ih,
                                            bs_ih, bs_hh, bp_ih, bp_hh, bd_ih, bd_hh);
    enc0_kernel<<<dim3(nPW, 2), 256>>>(speed, pos);

    for (int t = 1; t < TSTEPS; ++t)
        gemm_step<<<dim3(NGATE / 128, BATCH / 128, 2), 256>>>(
            0, t & 1, (t + 1) & 1, t, speed, pos);

    combine_kernel<<<nPW, 256>>>(pos);

    for (int t = 0; t < TSTEPS; ++t) {
        gemm_step<<<dim3(NGATE / 128, BATCH / 128, 1), 256>>>(
            1, t & 1, (t + 1) & 1, t, speed, pos);
        dec_tail_kernel<<<BATCH, 512>>>(W_fc, b_fc, W_emb, b_emb, out, t);
    }
}

// round 14
// speedup vs baseline: 2.5797x; 1.1098x over previous
#include <cuda_runtime.h>
#include <cuda_bf16.h>
#include <cstdint>

#define BATCH 8192
#define TSTEPS 16
#define HID 512
#define FEAT 4
#define NGATE 2048  // 4*HID

// ---------------- static device scratch (no dynamic allocation) -------------
// h16: [buf][net][B*H], double-buffered per step (net: 0=enc_s, 1=enc_p, 2=dec)
__device__ __nv_bfloat16 g_h16[2][3][BATCH * HID];
__device__ float         g_h32[3][BATCH * HID];     // fp32 h (combine / dec tail)
__device__ float         g_cst[3][BATCH * HID];     // c state
__device__ __nv_bfloat16 g_W16[3][NGATE * HID];     // W_hh bf16, gate-interleaved rows
__device__ float         g_bias[3][NGATE];          // b_ih+b_hh, permuted
__device__ float         g_Wih[3][NGATE * FEAT];    // W_ih rows, permuted
__device__ float         g_lastpos[BATCH * FEAT];

// ---------------- sm_80-level PTX helpers (base target sm_103) --------------
static __device__ __forceinline__ uint32_t smem_u32(const void* p) {
    return (uint32_t)__cvta_generic_to_shared(p);
}
#define CP_ASYNC16(dst, src) \
    asm volatile("cp.async.cg.shared.global [%0], [%1], 16;" :: "r"(dst), "l"(src))
#define CP_COMMIT() asm volatile("cp.async.commit_group;" ::: "memory")
#define CP_WAIT0()  asm volatile("cp.async.wait_group 0;" ::: "memory")
#define CP_WAIT1()  asm volatile("cp.async.wait_group 1;" ::: "memory")

static __device__ __forceinline__ void ldsm_x4(uint32_t* r, uint32_t addr) {
    asm volatile("ldmatrix.sync.aligned.m8n8.x4.shared.b16 {%0,%1,%2,%3}, [%4];"
                 : "=r"(r[0]), "=r"(r[1]), "=r"(r[2]), "=r"(r[3]) : "r"(addr));
}
static __device__ __forceinline__ void ldsm_x2(uint32_t* r, uint32_t addr) {
    asm volatile("ldmatrix.sync.aligned.m8n8.x2.shared.b16 {%0,%1}, [%2];"
                 : "=r"(r[0]), "=r"(r[1]) : "r"(addr));
}
static __device__ __forceinline__ void mma_bf16(float* d, const uint32_t* a,
                                                const uint32_t* b) {
    asm volatile(
        "mma.sync.aligned.m16n8k16.row.col.f32.bf16.bf16.f32 "
        "{%0,%1,%2,%3}, {%4,%5,%6,%7}, {%8,%9}, {%0,%1,%2,%3};"
        : "+f"(d[0]), "+f"(d[1]), "+f"(d[2]), "+f"(d[3])
        : "r"(a[0]), "r"(a[1]), "r"(a[2]), "r"(a[3]), "r"(b[0]), "r"(b[1]));
}
static __device__ __forceinline__ uint32_t sw64(uint32_t off) {
    return off ^ ((off >> 3) & 0x30);
}
// Fast MUFU-based sigmoid/tanh (rel err ~2^-21; gate tolerance is 1e-3).
static __device__ __forceinline__ float sigf(float x) {
    return __fdividef(1.0f, 1.0f + __expf(-x));
}
static __device__ __forceinline__ float tanh_fast(float x) {
    return __fmaf_rn(2.0f, __fdividef(1.0f, 1.0f + __expf(-2.0f * x)), -1.0f);
}

// ---------------------------------------------------------------------------
// Fused GEMM + LSTM cell step.  3-stage cp.async pipeline (CP_WAIT0 on the
// final chunk), 2 CTAs/SM.  D[m,n'] = sum_k h[m,k]*Wp[n',k], n' = j*4+gi.
// Epilogue fully coalesced via smem staging; transcendentals are MUFU-fast.
// mode 0: encoders (blockIdx.z = net 0/1); mode 1: decoder (net 2, x=lastpos).
// ---------------------------------------------------------------------------
__global__ void __launch_bounds__(256, 2)
gemm_step(int mode, int srcbuf, int dstbuf, int t,
          const float* __restrict__ speed, const float* __restrict__ pos)
{
    const int net = (mode == 0) ? (int)blockIdx.z : 2;
    const __nv_bfloat16* A = g_h16[srcbuf][net];
    const __nv_bfloat16* W = g_W16[net];

    const int n0 = blockIdx.x * 128;
    const int jbase = blockIdx.x * 32;          // j range covered by this CTA
    const int m0 = blockIdx.y * 128;
    const int tid  = threadIdx.x;
    const int lane = tid & 31;
    const int warp = tid >> 5;
    const int wm = warp >> 2;   // 0..1
    const int wn = warp & 3;    // 0..3

    __shared__ __align__(1024) unsigned char sm[49152];  // 3 stages x 16KB
    const uint32_t smBase = smem_u32(sm);

    const uint4* A4 = reinterpret_cast<const uint4*>(A);
    const uint4* W4 = reinterpret_cast<const uint4*>(W);

    const int cu  = tid & 3;
    const int cr0 = tid >> 2;
    const uint32_t swoA0 = sw64((uint32_t)(cr0 * 64 + cu * 16));
    const uint32_t swoA1 = sw64((uint32_t)((cr0 + 64) * 64 + cu * 16));

    uint32_t aOff[4][2], bOff[4][2];
    {
        int l = lane;
        #pragma unroll
        for (int fm = 0; fm < 4; ++fm) {
            int r = wm * 64 + fm * 16 + (l & 15);
            #pragma unroll
            for (int kk = 0; kk < 2; ++kk)
                aOff[fm][kk] = sw64((uint32_t)(r * 64 + kk * 32 + ((l >> 4) & 1) * 16));
        }
        int l2 = lane & 15;
        #pragma unroll
        for (int fn = 0; fn < 4; ++fn) {
            int r = wn * 32 + fn * 8 + (l2 & 7);
            #pragma unroll
            for (int kk = 0; kk < 2; ++kk)
                bOff[fn][kk] =
                    8192u + sw64((uint32_t)(r * 64 + kk * 32 + ((l2 >> 3) & 1) * 16));
        }
    }

    float d[4][4][4];
    #pragma unroll
    for (int i = 0; i < 4; ++i)
        #pragma unroll
        for (int j = 0; j < 4; ++j)
            #pragma unroll
            for (int q = 0; q < 4; ++q) d[i][j][q] = 0.0f;

    auto issue = [&](int ch, int stage) {
        uint32_t st = smBase + (uint32_t)(stage * 16384);
        int ko = ch * 4;
        CP_ASYNC16(st + swoA0,         (const void*)(A4 + (size_t)(m0 + cr0)      * 64 + ko + cu));
        CP_ASYNC16(st + swoA1,         (const void*)(A4 + (size_t)(m0 + cr0 + 64) * 64 + ko + cu));
        CP_ASYNC16(st + 8192u + swoA0, (const void*)(W4 + (size_t)(n0 + cr0)      * 64 + ko + cu));
        CP_ASYNC16(st + 8192u + swoA1, (const void*)(W4 + (size_t)(n0 + cr0 + 64) * 64 + ko + cu));
        CP_COMMIT();
    };

    issue(0, 0);
    issue(1, 1);

    int stage = 0;
    for (int c = 0; c < 16; ++c) {
        if (c < 15) { CP_WAIT1(); }   // chunk c complete; chunk c+1 may be in flight
        else        { CP_WAIT0(); }   // FINAL chunk: must drain fully
        __syncthreads();              // chunk-c data visible; prev compute done
        if (c < 14) {
            int s2 = stage + 2; if (s2 >= 3) s2 -= 3;
            issue(c + 2, s2);
        }

        const uint32_t st = smBase + (uint32_t)(stage * 16384);
        #pragma unroll
        for (int kk = 0; kk < 2; ++kk) {
            uint32_t a[4][4], b[4][2];
            #pragma unroll
            for (int fm = 0; fm < 4; ++fm) ldsm_x4(a[fm], st + aOff[fm][kk]);
            #pragma unroll
            for (int fn = 0; fn < 4; ++fn) ldsm_x2(b[fn], st + bOff[fn][kk]);
            #pragma unroll
            for (int fm = 0; fm < 4; ++fm)
                #pragma unroll
                for (int fn = 0; fn < 4; ++fn) mma_bf16(d[fm][fn], a[fm], b[fn]);
        }
        if (++stage == 3) stage = 0;
    }
    __syncthreads();   // all compute + cp.async done before smem reuse below

    // ---- fused epilogue, fully coalesced via smem staging ------------------
    // layout (bytes): cbuf[128][33] @0 (16896), hbuf[128][33] @16896 (16896),
    //                 smx[512] @33792, smb[128] @35840, smw[512] @36352
    float* cbuf = reinterpret_cast<float*>(sm);
    float* hbuf = reinterpret_cast<float*>(sm + 16896);
    float* smx  = reinterpret_cast<float*>(sm + 33792);
    float* smb  = reinterpret_cast<float*>(sm + 35840);
    float* smw  = reinterpret_cast<float*>(sm + 36352);

    float* cstate = g_cst[net];
    float* h32    = g_h32[net];
    __nv_bfloat16* hdst = g_h16[dstbuf][net];

    // Phase A: coalesced loads of c_old block + x, bias, Wih
    #pragma unroll
    for (int i = 0; i < 16; ++i) {
        int idx = tid + i * 256;             // 0..4095
        int r = idx >> 5, cc = idx & 31;
        cbuf[r * 33 + cc] = cstate[(size_t)(m0 + r) * HID + jbase + cc];
    }
    if (tid < 128) smb[tid] = g_bias[net][n0 + tid];
    {
        const float* xb = (mode == 0) ? (net ? pos : speed) : nullptr;
        #pragma unroll
        for (int i = 0; i < 2; ++i) {
            int idx = tid + i * 256;         // 0..511
            smw[idx] = g_Wih[net][n0 * 4 + idx];
            int rr = idx >> 2, q = idx & 3;
            smx[idx] = (mode == 0)
                ? xb[(size_t)(m0 + rr) * (TSTEPS * FEAT) + t * FEAT + q]
                : g_lastpos[(m0 + rr) * 4 + q];
        }
    }
    __syncthreads();

    // Phase B: cell updates entirely in registers/smem (fast transcendentals)
    const int rbase = wm * 64 + (lane >> 2);
    const int odd   = lane & 1;
    #pragma unroll
    for (int fm = 0; fm < 4; ++fm) {
        #pragma unroll
        for (int fn = 0; fn < 4; ++fn) {
            const int cl = wn * 32 + fn * 8 + (lane & 3) * 2;  // local col n'
            const float b0 = smb[cl], b1 = smb[cl + 1];
            float v[2][2];
            #pragma unroll
            for (int half = 0; half < 2; ++half) {
                const int rloc = rbase + fm * 16 + half * 8;
                const float x0 = smx[rloc * 4 + 0], x1 = smx[rloc * 4 + 1];
                const float x2 = smx[rloc * 4 + 2], x3 = smx[rloc * 4 + 3];
                v[half][0] = d[fm][fn][half * 2 + 0] + b0
                           + x0 * smw[cl * 4 + 0] + x1 * smw[cl * 4 + 1]
                           + x2 * smw[cl * 4 + 2] + x3 * smw[cl * 4 + 3];
                v[half][1] = d[fm][fn][half * 2 + 1] + b1
                           + x0 * smw[(cl + 1) * 4 + 0] + x1 * smw[(cl + 1) * 4 + 1]
                           + x2 * smw[(cl + 1) * 4 + 2] + x3 * smw[(cl + 1) * 4 + 3];
            }
            // exchange with lane^1: even lanes own (i,f), odd lanes own (g,o)
            float q00 = __shfl_xor_sync(0xFFFFFFFFu, v[0][0], 1);
            float q01 = __shfl_xor_sync(0xFFFFFFFFu, v[0][1], 1);
            float q10 = __shfl_xor_sync(0xFFFFFFFFu, v[1][0], 1);
            float q11 = __shfl_xor_sync(0xFFFFFFFFu, v[1][1], 1);
            float gi_, gf_, gg_, go_;
            int jcl;
            if (!odd) { gi_ = v[0][0]; gf_ = v[0][1]; gg_ = q00; go_ = q01; jcl = cl; }
            else      { gi_ = q10;     gf_ = q11;     gg_ = v[1][0]; go_ = v[1][1]; jcl = cl - 2; }
            const int rloc = rbase + fm * 16 + odd * 8;
            const int jloc = jcl >> 2;                  // 0..31
            const int si = rloc * 33 + jloc;
            float cold = cbuf[si];
            float cn = sigf(gf_) * cold + sigf(gi_) * tanh_fast(gg_);
            float h  = sigf(go_) * tanh_fast(cn);
            cbuf[si] = cn;                              // in-place: touched once
            hbuf[si] = h;
        }
    }
    __syncthreads();

    // Phase C: coalesced stores of c, h16 (h32 only where it is ever read:
    // decoder every step, encoders only at the final step before combine)
    const int need_h32 = (mode == 1) || (t == TSTEPS - 1);
    #pragma unroll
    for (int i = 0; i < 16; ++i) {
        int idx = tid + i * 256;
        int r = idx >> 5, cc = idx & 31;
        float cv = cbuf[r * 33 + cc];
        float hv = hbuf[r * 33 + cc];
        size_t gidx = (size_t)(m0 + r) * HID + jbase + cc;
        cstate[gidx] = cv;
        if (need_h32) h32[gidx] = hv;
        hdst[gidx]   = __float2bfloat16(hv);
    }
}

// ---------------------------------------------------------------------------
// prep: permute W_hh rows to n'=j*4+gi (bf16); bias/Wih permuted by row `lin`.
// ---------------------------------------------------------------------------
__global__ void __launch_bounds__(256)
prep_kernel(const float* __restrict__ Ws_hh, const float* __restrict__ Wp_hh,
            const float* __restrict__ Wd_hh,
            const float* __restrict__ Ws_ih, const float* __restrict__ Wp_ih,
            const float* __restrict__ Wd_ih,
            const float* __restrict__ bs_ih, const float* __restrict__ bs_hh,
            const float* __restrict__ bp_ih, const float* __restrict__ bp_hh,
            const float* __restrict__ bd_ih, const float* __restrict__ bd_hh)
{
    int lin = blockIdx.x * 256 + threadIdx.x;    // 0 .. NGATE*HID-1
    int np = lin / HID;                          // permuted row n'
    int k  = lin - np * HID;
    int j  = np >> 2, gi = np & 3;
    int n  = gi * HID + j;                       // original row
    size_t src = (size_t)n * HID + k;
    g_W16[0][lin] = __float2bfloat16(Ws_hh[src]);
    g_W16[1][lin] = __float2bfloat16(Wp_hh[src]);
    g_W16[2][lin] = __float2bfloat16(Wd_hh[src]);
    if (lin < NGATE) {
        int jj = lin >> 2, gg = lin & 3;
        int nn = gg * HID + jj;                  // original row for permuted row `lin`
        g_bias[0][lin] = bs_ih[nn] + bs_hh[nn];
        g_bias[1][lin] = bp_ih[nn] + bp_hh[nn];
        g_bias[2][lin] = bd_ih[nn] + bd_hh[nn];
        #pragma unroll
        for (int q = 0; q < 4; ++q) {
            g_Wih[0][lin * 4 + q] = Ws_ih[nn * 4 + q];
            g_Wih[1][lin * 4 + q] = Wp_ih[nn * 4 + q];
            g_Wih[2][lin * 4 + q] = Wd_ih[nn * 4 + q];
        }
    }
}

// Encoder step 0 (h=c=0): gates = bias + x.Wih ; writes c, h32, h16[1]
__global__ void __launch_bounds__(256)
enc0_kernel(const float* __restrict__ speed, const float* __restrict__ pos)
{
    const int e = blockIdx.y;
    const float* x = e ? pos : speed;
    int lin = blockIdx.x * 256 + threadIdx.x;
    int b = lin >> 9, j = lin & 511;

    const float* xr = x + b * (TSTEPS * FEAT);   // t = 0
    float x0 = xr[0], x1 = xr[1], x2 = xr[2], x3 = xr[3];

    float gate[4];
    #pragma unroll
    for (int gi = 0; gi < 4; ++gi) {
        int np = j * 4 + gi;
        const float* wr = &g_Wih[e][np * 4];
        gate[gi] = g_bias[e][np] + x0 * wr[0] + x1 * wr[1] + x2 * wr[2] + x3 * wr[3];
    }
    float cn = sigf(gate[0]) * tanh_fast(gate[2]);   // c_old = 0
    float h  = sigf(gate[3]) * tanh_fast(cn);
    g_cst[e][lin] = cn;
    g_h32[e][lin] = h;
    g_h16[1][e][lin] = __float2bfloat16(h);
}

__global__ void __launch_bounds__(256)
combine_kernel(const float* __restrict__ pos)
{
    int lin = blockIdx.x * 256 + threadIdx.x;
    g_h16[0][2][lin] = __float2bfloat16(g_h32[0][lin] + g_h32[1][lin]);
    g_cst[2][lin] = g_cst[0][lin] + g_cst[1][lin];
    int b = lin >> 9, j = lin & 511;
    if (j < FEAT)
        g_lastpos[b * FEAT + j] = pos[b * (TSTEPS * FEAT) + (TSTEPS - 1) * FEAT + j];
}

// Decoder tail: fc reduce + softmax + emb + lastpos update (reads h32[2])
__global__ void __launch_bounds__(512)
dec_tail_kernel(const float* __restrict__ W_fc, const float* __restrict__ b_fc,
                const float* __restrict__ W_emb, const float* __restrict__ b_emb,
                float* __restrict__ out, int t)
{
    const int b = blockIdx.x;
    const int j = threadIdx.x;
    float h = g_h32[2][(size_t)b * HID + j];

    float s0 = h * W_fc[j];
    float s1 = h * W_fc[HID + j];
    #pragma unroll
    for (int off = 16; off > 0; off >>= 1) {
        s0 += __shfl_xor_sync(0xFFFFFFFFu, s0, off);
        s1 += __shfl_xor_sync(0xFFFFFFFFu, s1, off);
    }
    __shared__ float r0[16], r1[16];
    if ((j & 31) == 0) { r0[j >> 5] = s0; r1[j >> 5] = s1; }
    __syncthreads();
    if (j == 0) {
        float t0 = 0.f, t1 = 0.f;
        #pragma unroll
        for (int w = 0; w < 16; ++w) { t0 += r0[w]; t1 += r1[w]; }
        float c0 = fmaxf(t0 + b_fc[0], 0.f);
        float c1 = fmaxf(t1 + b_fc[1], 0.f);
        float m = fmaxf(c0, c1);
        float e0 = expf(c0 - m), e1 = expf(c1 - m);
        float inv = 1.f / (e0 + e1);
        out[((size_t)b * TSTEPS + t) * 2 + 0] = e0 * inv;
        out[((size_t)b * TSTEPS + t) * 2 + 1] = e1 * inv;
        #pragma unroll
        for (int k = 0; k < 4; ++k)
            g_lastpos[b * 4 + k] =
                fmaxf(c0 * W_emb[k * 2 + 0] + c1 * W_emb[k * 2 + 1] + b_emb[k], 0.f);
    }
}

// ---------------- orchestration ---------------------------------------------
extern "C" void kernel_launch(void* const* d_in, const int* in_sizes, int n_in,
                              void* d_out, int out_size)
{
    (void)in_sizes; (void)n_in; (void)out_size;
    const float* speed = (const float*)d_in[0];
    const float* pos   = (const float*)d_in[1];
    const float* Ws_ih = (const float*)d_in[2];
    const float* Ws_hh = (const float*)d_in[3];
    const float* bs_ih = (const float*)d_in[4];
    const float* bs_hh = (const float*)d_in[5];
    const float* Wp_ih = (const float*)d_in[6];
    const float* Wp_hh = (const float*)d_in[7];
    const float* bp_ih = (const float*)d_in[8];
    const float* bp_hh = (const float*)d_in[9];
    const float* Wd_ih = (const float*)d_in[10];
    const float* Wd_hh = (const float*)d_in[11];
    const float* bd_ih = (const float*)d_in[12];
    const float* bd_hh = (const float*)d_in[13];
    const float* W_fc  = (const float*)d_in[14];
    const float* b_fc  = (const float*)d_in[15];
    const float* W_emb = (const float*)d_in[16];
    const float* b_emb = (const float*)d_in[17];
    float* out = (float*)d_out;

    const int nPW = (BATCH * HID) / 256;   // 16384 blocks

    prep_kernel<<<NGATE * HID / 256, 256>>>(Ws_hh, Wp_hh, Wd_hh,
                                            Ws_ih, Wp_ih, Wd_ih,
                                            bs_ih, bs_hh, bp_ih, bp_hh, bd_ih, bd_hh);
    enc0_kernel<<<dim3(nPW, 2), 256>>>(speed, pos);

    for (int t = 1; t < TSTEPS; ++t)
        gemm_step<<<dim3(NGATE / 128, BATCH / 128, 2), 256>>>(
            0, t & 1, (t + 1) & 1, t, speed, pos);

    combine_kernel<<<nPW, 256>>>(pos);

    for (int t = 0; t < TSTEPS; ++t) {
        gemm_step<<<dim3(NGATE / 128, BATCH / 128, 1), 256>>>(
            1, t & 1, (t + 1) & 1, t, speed, pos);
        dec_tail_kernel<<<BATCH, 512>>>(W_fc, b_fc, W_emb, b_emb, out, t);
    }
}